// round 12
// baseline (speedup 1.0000x reference)
#include <cuda_runtime.h>
#include <cuda_bf16.h>

#define B_    4
#define C_    256
#define HW_   9216
#define N_    4608
#define FOUT_ 32
#define DV_   256
#define TOT_  (B_ * C_ * HW_)
#define NT_   72            // kv tiles of 64

// ---- scratch ----
__device__ __align__(16) __nv_bfloat16 g_Q[B_ * N_ * FOUT_];  // (b,n,32)
__device__ __align__(16) __nv_bfloat16 g_K[B_ * N_ * FOUT_];  // (b,n,32)
__device__ __align__(16) __nv_bfloat16 g_V[B_ * N_ * DV_];    // (b,n,256)
__device__ float g_O[B_ * N_ * DV_];
__device__ __align__(16) int g_map[HW_];   // zero-init; stores slot+1 (0 = none)

// ============================================================
// helpers (base-ISA only: ldmatrix + mma.sync, legal on compute_103)
// ============================================================
__device__ __forceinline__ unsigned smem_u32(const void* p) {
    unsigned a;
    asm("{ .reg .u64 t; cvta.to.shared.u64 t, %1; cvt.u32.u64 %0, t; }" : "=r"(a) : "l"(p));
    return a;
}
__device__ __forceinline__ void cpa16(unsigned dst, const void* src) {
    asm volatile("cp.async.cg.shared.global [%0], [%1], 16;" :: "r"(dst), "l"(src));
}
#define CP_COMMIT() asm volatile("cp.async.commit_group;" ::: "memory")
#define CP_WAIT1()  asm volatile("cp.async.wait_group 1;" ::: "memory")

__device__ __forceinline__ void ldsm4(unsigned* r, unsigned a) {
    asm volatile("ldmatrix.sync.aligned.m8n8.x4.shared.b16 {%0,%1,%2,%3}, [%4];"
        : "=r"(r[0]), "=r"(r[1]), "=r"(r[2]), "=r"(r[3]) : "r"(a));
}
__device__ __forceinline__ void ldsm4t(unsigned* r, unsigned a) {
    asm volatile("ldmatrix.sync.aligned.m8n8.x4.trans.shared.b16 {%0,%1,%2,%3}, [%4];"
        : "=r"(r[0]), "=r"(r[1]), "=r"(r[2]), "=r"(r[3]) : "r"(a));
}
// D = A@B + D, m16n8k16, bf16 in, fp32 accum
__device__ __forceinline__ void mma16816(float* c, const unsigned* a, const unsigned* b) {
    asm volatile("mma.sync.aligned.m16n8k16.row.col.f32.bf16.bf16.f32 "
        "{%0,%1,%2,%3}, {%4,%5,%6,%7}, {%8,%9}, {%0,%1,%2,%3};"
        : "+f"(c[0]), "+f"(c[1]), "+f"(c[2]), "+f"(c[3])
        : "r"(a[0]), "r"(a[1]), "r"(a[2]), "r"(a[3]), "r"(b[0]), "r"(b[1]));
}
__device__ __forceinline__ unsigned pack_bf16x2(float lo, float hi) {
    unsigned r;
    asm("cvt.rn.bf16x2.f32 %0, %1, %2;" : "=r"(r) : "f"(hi), "f"(lo));  // hi<<16 | lo
    return r;
}

// ============================================================
// scatter map: one launch; g_map zero-init, store slot+1
// ============================================================
__global__ void map_set_kernel(const int* __restrict__ idx_out) {
    int n = blockIdx.x * blockDim.x + threadIdx.x;
    if (n < N_) g_map[idx_out[n]] = n + 1;
}

// ============================================================
// HMMA projection body (unchanged from round 9)
// ============================================================
template<int OTILE>
__device__ __forceinline__ void proj_body(
    const float* __restrict__ f, const int* __restrict__ idx,
    const float* __restrict__ W, const float* __restrict__ bias,
    __nv_bfloat16* outp, int osize, int o0, int b, int n0)
{
    extern __shared__ __align__(128) char ps[];
    const unsigned sb = smem_u32(ps);
    const unsigned ws = sb;                       // OTILE*512 bytes
    const unsigned xs = sb + OTILE * 512;         // 2 x 16384 bytes
    int* sidx = (int*)(ps + OTILE * 512 + 32768);

    const int tid = threadIdx.x, wid = tid >> 5, lane = tid & 31;

    constexpr int OW = (OTILE == 128) ? 4 : OTILE / 32;  // o-warps
    constexpr int MW = 8 / OW;                           // m-warps
    constexpr int MT = 128 / (MW * 16);                  // m-tiles per warp
    const int mw = wid % MW;
    const int ow = wid / MW;
    const int mbase = mw * 16 * MT;

    if (tid < 128) sidx[tid] = idx[n0 + tid];

    for (int o = wid; o < OTILE; o += 8) {
#pragma unroll
        for (int h = 0; h < 2; h++) {
            float4 wv = *(const float4*)&W[(size_t)(o0 + o) * C_ + (lane + 32 * h) * 4];
            unsigned p0 = pack_bf16x2(wv.x, wv.y);
            unsigned p1 = pack_bf16x2(wv.z, wv.w);
            int ch = (lane >> 1) + 16 * h;
            *(uint2*)(ps + o * 512 + ((ch ^ (o & 7)) * 16) + (lane & 1) * 8)
                = make_uint2(p0, p1);
        }
    }
    __syncthreads();

    const int gn  = tid & 127;
    const int gcb = tid >> 7;
    const float* fb = f + (size_t)b * C_ * HW_;
    const int gidx = sidx[gn];

    unsigned gr[4][4];
    auto do_gather = [&](int c0) {
#pragma unroll
        for (int i = 0; i < 4; i++) {
            int cbase = c0 + (gcb + 2 * i) * 8;
#pragma unroll
            for (int j = 0; j < 4; j++) {
                float a0 = fb[(size_t)(cbase + 2 * j)     * HW_ + gidx];
                float a1 = fb[(size_t)(cbase + 2 * j + 1) * HW_ + gidx];
                gr[i][j] = pack_bf16x2(a0, a1);
            }
        }
    };
    auto do_sts = [&](int buf) {
#pragma unroll
        for (int i = 0; i < 4; i++) {
            int ch = gcb + 2 * i;
            *(uint4*)(ps + OTILE * 512 + buf * 16384 + gn * 128 + ((ch ^ (gn & 7)) * 16))
                = make_uint4(gr[i][0], gr[i][1], gr[i][2], gr[i][3]);
        }
    };

    do_gather(0);
    do_sts(0);
    __syncthreads();

    float acc[MT][4][4];
#pragma unroll
    for (int mt = 0; mt < MT; mt++)
#pragma unroll
        for (int ot = 0; ot < 4; ot++)
#pragma unroll
            for (int j = 0; j < 4; j++) acc[mt][ot][j] = 0.0f;

    for (int c4 = 0; c4 < 4; c4++) {
        const int buf = c4 & 1;
        if (c4 < 3) do_gather((c4 + 1) * 64);

        const unsigned xb = xs + buf * 16384;
#pragma unroll
        for (int s = 0; s < 4; s++) {
            unsigned bf[2][4];
#pragma unroll
            for (int oh = 0; oh < 2; oh++) {
                int row = ow * 32 + oh * 16 + (lane & 15);
                int ch  = c4 * 8 + 2 * s + (lane >> 4);
                ldsm4(bf[oh], ws + row * 512 + ((ch ^ (row & 7)) * 16));
            }
#pragma unroll
            for (int mt = 0; mt < MT; mt++) {
                unsigned af[4];
                int row = mbase + 16 * mt + (lane & 15);
                int ch  = 2 * s + (lane >> 4);
                ldsm4(af, xb + row * 128 + ((ch ^ (row & 7)) * 16));
                unsigned b0[2] = { bf[0][0], bf[0][2] };
                unsigned b1[2] = { bf[0][1], bf[0][3] };
                unsigned b2[2] = { bf[1][0], bf[1][2] };
                unsigned b3[2] = { bf[1][1], bf[1][3] };
                mma16816(acc[mt][0], af, b0);
                mma16816(acc[mt][1], af, b1);
                mma16816(acc[mt][2], af, b2);
                mma16816(acc[mt][3], af, b3);
            }
        }
        if (c4 < 3) do_sts(buf ^ 1);
        __syncthreads();
    }

#pragma unroll
    for (int mt = 0; mt < MT; mt++) {
        int r0 = mbase + 16 * mt + (lane >> 2);
#pragma unroll
        for (int ot = 0; ot < 4; ot++) {
            int oc = o0 + ow * 32 + ot * 8 + 2 * (lane & 3);
            float bb0 = bias[oc], bb1 = bias[oc + 1];
            __nv_bfloat162 v0 = __floats2bfloat162_rn(acc[mt][ot][0] + bb0,
                                                      acc[mt][ot][1] + bb1);
            __nv_bfloat162 v1 = __floats2bfloat162_rn(acc[mt][ot][2] + bb0,
                                                      acc[mt][ot][3] + bb1);
            *(__nv_bfloat162*)&outp[(size_t)(b * N_ + n0 + r0)     * osize + oc] = v0;
            *(__nv_bfloat162*)&outp[(size_t)(b * N_ + n0 + r0 + 8) * osize + oc] = v1;
        }
    }
}

__global__ void __launch_bounds__(256) proj_qk_kernel(
    const float* __restrict__ f,
    const int* __restrict__ idx_out, const float* __restrict__ Wq, const float* __restrict__ bq,
    const int* __restrict__ idx_in,  const float* __restrict__ Wk, const float* __restrict__ bk)
{
    const int sel = blockIdx.y;
    proj_body<32>(f,
                  sel ? idx_in : idx_out,
                  sel ? Wk : Wq,
                  sel ? bk : bq,
                  sel ? g_K : g_Q,
                  FOUT_, 0, blockIdx.z, blockIdx.x * 128);
}

__global__ void __launch_bounds__(256) proj_v_kernel(
    const float* __restrict__ f, const int* __restrict__ idx_in,
    const float* __restrict__ Wv, const float* __restrict__ bv)
{
    proj_body<128>(f, idx_in, Wv, bv, g_V, DV_,
                   blockIdx.y * 128, blockIdx.z, blockIdx.x * 128);
}

// ============================================================
// HMMA flash attention, BQ=128, 512 threads (16 warps = 4/SMSP).
// warp (r=wid&7, cw=wid>>3): rows 16r..16r+15, d-cols 128cw..+127.
// Split-S: warp computes kv chunks {2cw, 2cw+1} only; P via SMEM exchange.
// acc = 64 regs/thread (fixes R11's 252-reg pressure).
// SMEM: Q 128x80 | K 2x 64x80 | V 2x 64x528 | Pex 16K  = 104448 B
// ============================================================
#define QSTR  80
#define VSTR  528
#define SM_Q  0
#define SM_K  10240
#define KBUF  5120
#define SM_V  20480
#define VBUF  33792
#define SM_PX 88064
#define SM_TOT 104448
#define NTHR  512

__device__ __forceinline__ void load_kv(unsigned sb, int b, int t, int buf) {
    const int tid = threadIdx.x;
    if (tid < 256) {   // K tile: 64 rows x 4 chunks
        int row = tid >> 2, c = tid & 3;
        cpa16(sb + SM_K + buf * KBUF + row * QSTR + c * 16,
              g_K + ((size_t)b * N_ + t * 64 + row) * FOUT_ + c * 8);
    }
    const __nv_bfloat16* vg = g_V + ((size_t)b * N_ + t * 64) * DV_;
#pragma unroll
    for (int i = 0; i < 4; i++) {   // V tile: 64 rows x 32 chunks
        int e = tid + i * NTHR;
        int row = e >> 5, c = e & 31;
        cpa16(sb + SM_V + buf * VBUF + row * VSTR + c * 16, vg + row * DV_ + c * 8);
    }
}

__global__ void __launch_bounds__(NTHR) flash_mma_kernel() {
    extern __shared__ __align__(128) char smem[];
    const unsigned sb = smem_u32(smem);
    const int tid  = threadIdx.x;
    const int wid  = tid >> 5, lane = tid & 31;
    const int r    = wid & 7;          // q-row group of 16
    const int cw   = wid >> 3;         // d half / S-chunk half
    const int gid  = lane >> 2, tig = lane & 3;
    const int b    = blockIdx.y;
    const int q0   = blockIdx.x * 128;

    // Q tile: 128 rows x 4 chunks = 512 cp.async (one per thread)
    {
        int row = tid >> 2, c = tid & 3;
        cpa16(sb + SM_Q + row * QSTR + c * 16,
              g_Q + ((size_t)b * N_ + q0 + row) * FOUT_ + c * 8);
    }
    load_kv(sb, b, 0, 0);
    CP_COMMIT();

    float acc[16][4];
#pragma unroll
    for (int i = 0; i < 16; i++)
#pragma unroll
        for (int j = 0; j < 4; j++) acc[i][j] = 0.0f;
    float rs0 = 0.0f, rs1 = 0.0f;      // rows gid, gid+8
    unsigned qf[2][4];
    unsigned Pm[2][4], Po[2][4];       // own / partner chunk fragments

    const unsigned vrow = (lane & 7) + ((lane >> 3) & 1) * 8;
    const unsigned vcolb = (cw * 128 + (lane >> 4) * 8) * 2;

    for (int t = 0; t < NT_; t++) {
        const int cur = t & 1;
        if (t + 1 < NT_) load_kv(sb, b, t + 1, cur ^ 1);
        CP_COMMIT();
        CP_WAIT1();                  // tile t (and Q) resident
        __syncthreads();

        if (t == 0) {
            unsigned qbase = sb + SM_Q + (16 * r + (lane & 15)) * QSTR;
            ldsm4(qf[0], qbase + (lane >> 4) * 16);
            ldsm4(qf[1], qbase + 32 + (lane >> 4) * 16);
        }

        // ---- my half of S (+exp): chunks {2cw, 2cw+1} for my 16 rows ----
        const unsigned kb = sb + SM_K + cur * KBUF;
#pragma unroll
        for (int jj = 0; jj < 2; jj++) {
            const int j = 2 * cw + jj;           // global kv chunk
            unsigned kfa[4], kfb[4];
            ldsm4(kfa, kb + (j * 16 +     (lane & 7)) * QSTR + ((lane >> 3) * 8) * 2);
            ldsm4(kfb, kb + (j * 16 + 8 + (lane & 7)) * QSTR + ((lane >> 3) * 8) * 2);
            float Sa[4] = {0.f, 0.f, 0.f, 0.f};
            float Sb[4] = {0.f, 0.f, 0.f, 0.f};
            mma16816(Sa, qf[0], kfa);
            mma16816(Sa, qf[1], kfa + 2);
            mma16816(Sb, qf[0], kfb);
            mma16816(Sb, qf[1], kfb + 2);
            float e0 = __expf(Sa[0]), e1 = __expf(Sa[1]);
            float e2 = __expf(Sa[2]), e3 = __expf(Sa[3]);
            float e4 = __expf(Sb[0]), e5 = __expf(Sb[1]);
            float e6 = __expf(Sb[2]), e7 = __expf(Sb[3]);
            rs0 += (e0 + e1) + (e4 + e5);
            rs1 += (e2 + e3) + (e6 + e7);
            Pm[jj][0] = pack_bf16x2(e0, e1);
            Pm[jj][1] = pack_bf16x2(e2, e3);
            Pm[jj][2] = pack_bf16x2(e4, e5);
            Pm[jj][3] = pack_bf16x2(e6, e7);
            *(uint4*)(smem + SM_PX + (r * 4 + j) * 512 + lane * 16)
                = make_uint4(Pm[jj][0], Pm[jj][1], Pm[jj][2], Pm[jj][3]);
        }
        __syncthreads();             // P exchange visible

        // partner's chunks (lane-for-lane identical fragment layout)
#pragma unroll
        for (int jj = 0; jj < 2; jj++) {
            const int jo = 2 * (1 - cw) + jj;
            uint4 v = *(const uint4*)(smem + SM_PX + (r * 4 + jo) * 512 + lane * 16);
            Po[jj][0] = v.x; Po[jj][1] = v.y; Po[jj][2] = v.z; Po[jj][3] = v.w;
        }

        // ---- O += P V over all 4 chunks (own two, then partner two) ----
        const unsigned vb = sb + SM_V + cur * VBUF;
        auto pv_step = [&](int j, const unsigned* P2) {
#pragma unroll
            for (int p = 0; p < 8; p++) {
                unsigned vf[4];
                ldsm4t(vf, vb + (16 * j + vrow) * VSTR + vcolb + p * 32);
                mma16816(acc[2 * p],     P2, vf);
                mma16816(acc[2 * p + 1], P2, vf + 2);
            }
        };
#pragma unroll
        for (int jj = 0; jj < 2; jj++) pv_step(2 * cw + jj,       Pm[jj]);
#pragma unroll
        for (int jj = 0; jj < 2; jj++) pv_step(2 * (1 - cw) + jj, Po[jj]);

        __syncthreads();             // buffer + Pex reuse safe
    }

    // rowsum: quad reduce, then cross-cw reduce via SMEM
    rs0 += __shfl_xor_sync(0xFFFFFFFFu, rs0, 1);
    rs0 += __shfl_xor_sync(0xFFFFFFFFu, rs0, 2);
    rs1 += __shfl_xor_sync(0xFFFFFFFFu, rs1, 1);
    rs1 += __shfl_xor_sync(0xFFFFFFFFu, rs1, 2);
    {
        float2* rsx = (float2*)(smem + SM_PX);
        rsx[(cw * 8 + r) * 32 + lane] = make_float2(rs0, rs1);
        __syncthreads();
        float2 o = rsx[((1 - cw) * 8 + r) * 32 + lane];
        rs0 += o.x; rs1 += o.y;
    }
    float inv0 = 1.0f / rs0, inv1 = 1.0f / rs1;

    float* og = g_O + ((size_t)b * N_ + q0 + 16 * r + gid) * DV_ + cw * 128;
    float* og2 = og + 8 * DV_;
#pragma unroll
    for (int nt = 0; nt < 16; nt++) {
        int col = nt * 8 + 2 * tig;
        *(float2*)(og  + col) = make_float2(acc[nt][0] * inv0, acc[nt][1] * inv0);
        *(float2*)(og2 + col) = make_float2(acc[nt][2] * inv1, acc[nt][3] * inv1);
    }
}

// ============================================================
// Epilogue: 4 elements per thread; map stores slot+1 (0 = keep f)
// ============================================================
__global__ void __launch_bounds__(256) epilogue_kernel(
    const float* __restrict__ f, const float* __restrict__ mask,
    const float* __restrict__ gamma, float* __restrict__ out)
{
    int q = blockIdx.x * 256 + threadIdx.x;      // quad index
    int gid = q * 4;
    int hw = gid % HW_;
    int bc = gid / HW_;
    int c  = bc % C_;
    int b  = bc / C_;

    float4 fv = *(const float4*)(f + gid);
    int4  mp = *(const int4*)(g_map + hw);
    float4 mk = *(const float4*)(mask + b * HW_ + hw);
    float g = gamma[0];

    const float* ob = g_O + (size_t)b * N_ * DV_ + c;
    float4 val;
    val.x = (mp.x > 0) ? ob[(size_t)(mp.x - 1) * DV_] : fv.x;
    val.y = (mp.y > 0) ? ob[(size_t)(mp.y - 1) * DV_] : fv.y;
    val.z = (mp.z > 0) ? ob[(size_t)(mp.z - 1) * DV_] : fv.z;
    val.w = (mp.w > 0) ? ob[(size_t)(mp.w - 1) * DV_] : fv.w;

    float4 o2;
    o2.x = val.x * (1.0f + (1.0f - mk.x) * g);
    o2.y = val.y * (1.0f + (1.0f - mk.y) * g);
    o2.z = val.z * (1.0f + (1.0f - mk.z) * g);
    o2.w = val.w * (1.0f + (1.0f - mk.w) * g);

    *(float4*)(out + gid)        = val;
    *(float4*)(out + gid + TOT_) = o2;
}

// ============================================================
// launch
// ============================================================
extern "C" void kernel_launch(void* const* d_in, const int* in_sizes, int n_in,
                              void* d_out, int out_size) {
    const float* f       = (const float*)d_in[0];
    const float* mask    = (const float*)d_in[1];
    const int*   idx_out = (const int*)d_in[2];
    const int*   idx_in  = (const int*)d_in[3];
    const float* Wq      = (const float*)d_in[4];
    const float* bq      = (const float*)d_in[5];
    const float* Wk      = (const float*)d_in[6];
    const float* bk      = (const float*)d_in[7];
    const float* Wv      = (const float*)d_in[8];
    const float* bv      = (const float*)d_in[9];
    const float* gamma   = (const float*)d_in[10];
    float* out = (float*)d_out;

    const int SM_P32  = 32 * 512 + 32768 + 512;    // 49664
    const int SM_P128 = 128 * 512 + 32768 + 512;   // 98816
    cudaFuncSetAttribute(proj_qk_kernel,
                         cudaFuncAttributeMaxDynamicSharedMemorySize, SM_P32);
    cudaFuncSetAttribute(proj_v_kernel,
                         cudaFuncAttributeMaxDynamicSharedMemorySize, SM_P128);
    cudaFuncSetAttribute(flash_mma_kernel,
                         cudaFuncAttributeMaxDynamicSharedMemorySize, SM_TOT);

    map_set_kernel<<<(N_ + 255) / 256, 256>>>(idx_out);

    proj_qk_kernel<<<dim3(N_ / 128, 2, B_), 256, SM_P32>>>(
        f, idx_out, Wq, bq, idx_in, Wk, bk);
    proj_v_kernel<<<dim3(N_ / 128, DV_ / 128, B_), 256, SM_P128>>>(f, idx_in, Wv, bv);

    flash_mma_kernel<<<dim3(N_ / 128, B_), NTHR, SM_TOT>>>();

    epilogue_kernel<<<TOT_ / 4 / 256, 256>>>(f, mask, gamma, out);
}

// round 13
// speedup vs baseline: 1.0291x; 1.0291x over previous
#include <cuda_runtime.h>
#include <cuda_bf16.h>

#define B_    4
#define C_    256
#define HW_   9216
#define N_    4608
#define FOUT_ 32
#define DV_   256
#define TOT_  (B_ * C_ * HW_)
#define NT_   72            // kv tiles of 64

// ---- scratch ----
__device__ __align__(16) __nv_bfloat16 g_Q[B_ * N_ * FOUT_];  // (b,n,32)
__device__ __align__(16) __nv_bfloat16 g_K[B_ * N_ * FOUT_];  // (b,n,32)
__device__ __align__(16) __nv_bfloat16 g_V[B_ * N_ * DV_];    // (b,n,256)
__device__ float g_O[B_ * N_ * DV_];
__device__ __align__(16) int g_map[HW_];   // zero-init; stores slot+1 (0 = none)

// ============================================================
// helpers (base-ISA only: ldmatrix + mma.sync, legal on compute_103)
// ============================================================
__device__ __forceinline__ unsigned smem_u32(const void* p) {
    unsigned a;
    asm("{ .reg .u64 t; cvta.to.shared.u64 t, %1; cvt.u32.u64 %0, t; }" : "=r"(a) : "l"(p));
    return a;
}
__device__ __forceinline__ void cpa16(unsigned dst, const void* src) {
    asm volatile("cp.async.cg.shared.global [%0], [%1], 16;" :: "r"(dst), "l"(src));
}
#define CP_COMMIT() asm volatile("cp.async.commit_group;" ::: "memory")
#define CP_WAIT1()  asm volatile("cp.async.wait_group 1;" ::: "memory")

__device__ __forceinline__ void ldsm4(unsigned* r, unsigned a) {
    asm volatile("ldmatrix.sync.aligned.m8n8.x4.shared.b16 {%0,%1,%2,%3}, [%4];"
        : "=r"(r[0]), "=r"(r[1]), "=r"(r[2]), "=r"(r[3]) : "r"(a));
}
__device__ __forceinline__ void ldsm4t(unsigned* r, unsigned a) {
    asm volatile("ldmatrix.sync.aligned.m8n8.x4.trans.shared.b16 {%0,%1,%2,%3}, [%4];"
        : "=r"(r[0]), "=r"(r[1]), "=r"(r[2]), "=r"(r[3]) : "r"(a));
}
// D = A@B + D, m16n8k16, bf16 in, fp32 accum
__device__ __forceinline__ void mma16816(float* c, const unsigned* a, const unsigned* b) {
    asm volatile("mma.sync.aligned.m16n8k16.row.col.f32.bf16.bf16.f32 "
        "{%0,%1,%2,%3}, {%4,%5,%6,%7}, {%8,%9}, {%0,%1,%2,%3};"
        : "+f"(c[0]), "+f"(c[1]), "+f"(c[2]), "+f"(c[3])
        : "r"(a[0]), "r"(a[1]), "r"(a[2]), "r"(a[3]), "r"(b[0]), "r"(b[1]));
}
__device__ __forceinline__ unsigned pack_bf16x2(float lo, float hi) {
    unsigned r;
    asm("cvt.rn.bf16x2.f32 %0, %1, %2;" : "=r"(r) : "f"(hi), "f"(lo));  // hi<<16 | lo
    return r;
}

// ============================================================
// scatter map: one launch; g_map zero-init, store slot+1
// ============================================================
__global__ void map_set_kernel(const int* __restrict__ idx_out) {
    int n = blockIdx.x * blockDim.x + threadIdx.x;
    if (n < N_) g_map[idx_out[n]] = n + 1;
}

// ============================================================
// HMMA projection body (unchanged)
// ============================================================
template<int OTILE>
__device__ __forceinline__ void proj_body(
    const float* __restrict__ f, const int* __restrict__ idx,
    const float* __restrict__ W, const float* __restrict__ bias,
    __nv_bfloat16* outp, int osize, int o0, int b, int n0)
{
    extern __shared__ __align__(128) char ps[];
    const unsigned sb = smem_u32(ps);
    const unsigned ws = sb;                       // OTILE*512 bytes
    const unsigned xs = sb + OTILE * 512;         // 2 x 16384 bytes
    int* sidx = (int*)(ps + OTILE * 512 + 32768);

    const int tid = threadIdx.x, wid = tid >> 5, lane = tid & 31;

    constexpr int OW = (OTILE == 128) ? 4 : OTILE / 32;  // o-warps
    constexpr int MW = 8 / OW;                           // m-warps
    constexpr int MT = 128 / (MW * 16);                  // m-tiles per warp
    const int mw = wid % MW;
    const int ow = wid / MW;
    const int mbase = mw * 16 * MT;

    if (tid < 128) sidx[tid] = idx[n0 + tid];

    for (int o = wid; o < OTILE; o += 8) {
#pragma unroll
        for (int h = 0; h < 2; h++) {
            float4 wv = *(const float4*)&W[(size_t)(o0 + o) * C_ + (lane + 32 * h) * 4];
            unsigned p0 = pack_bf16x2(wv.x, wv.y);
            unsigned p1 = pack_bf16x2(wv.z, wv.w);
            int ch = (lane >> 1) + 16 * h;
            *(uint2*)(ps + o * 512 + ((ch ^ (o & 7)) * 16) + (lane & 1) * 8)
                = make_uint2(p0, p1);
        }
    }
    __syncthreads();

    const int gn  = tid & 127;
    const int gcb = tid >> 7;
    const float* fb = f + (size_t)b * C_ * HW_;
    const int gidx = sidx[gn];

    unsigned gr[4][4];
    auto do_gather = [&](int c0) {
#pragma unroll
        for (int i = 0; i < 4; i++) {
            int cbase = c0 + (gcb + 2 * i) * 8;
#pragma unroll
            for (int j = 0; j < 4; j++) {
                float a0 = fb[(size_t)(cbase + 2 * j)     * HW_ + gidx];
                float a1 = fb[(size_t)(cbase + 2 * j + 1) * HW_ + gidx];
                gr[i][j] = pack_bf16x2(a0, a1);
            }
        }
    };
    auto do_sts = [&](int buf) {
#pragma unroll
        for (int i = 0; i < 4; i++) {
            int ch = gcb + 2 * i;
            *(uint4*)(ps + OTILE * 512 + buf * 16384 + gn * 128 + ((ch ^ (gn & 7)) * 16))
                = make_uint4(gr[i][0], gr[i][1], gr[i][2], gr[i][3]);
        }
    };

    do_gather(0);
    do_sts(0);
    __syncthreads();

    float acc[MT][4][4];
#pragma unroll
    for (int mt = 0; mt < MT; mt++)
#pragma unroll
        for (int ot = 0; ot < 4; ot++)
#pragma unroll
            for (int j = 0; j < 4; j++) acc[mt][ot][j] = 0.0f;

    for (int c4 = 0; c4 < 4; c4++) {
        const int buf = c4 & 1;
        if (c4 < 3) do_gather((c4 + 1) * 64);

        const unsigned xb = xs + buf * 16384;
#pragma unroll
        for (int s = 0; s < 4; s++) {
            unsigned bf[2][4];
#pragma unroll
            for (int oh = 0; oh < 2; oh++) {
                int row = ow * 32 + oh * 16 + (lane & 15);
                int ch  = c4 * 8 + 2 * s + (lane >> 4);
                ldsm4(bf[oh], ws + row * 512 + ((ch ^ (row & 7)) * 16));
            }
#pragma unroll
            for (int mt = 0; mt < MT; mt++) {
                unsigned af[4];
                int row = mbase + 16 * mt + (lane & 15);
                int ch  = 2 * s + (lane >> 4);
                ldsm4(af, xb + row * 128 + ((ch ^ (row & 7)) * 16));
                unsigned b0[2] = { bf[0][0], bf[0][2] };
                unsigned b1[2] = { bf[0][1], bf[0][3] };
                unsigned b2[2] = { bf[1][0], bf[1][2] };
                unsigned b3[2] = { bf[1][1], bf[1][3] };
                mma16816(acc[mt][0], af, b0);
                mma16816(acc[mt][1], af, b1);
                mma16816(acc[mt][2], af, b2);
                mma16816(acc[mt][3], af, b3);
            }
        }
        if (c4 < 3) do_sts(buf ^ 1);
        __syncthreads();
    }

#pragma unroll
    for (int mt = 0; mt < MT; mt++) {
        int r0 = mbase + 16 * mt + (lane >> 2);
#pragma unroll
        for (int ot = 0; ot < 4; ot++) {
            int oc = o0 + ow * 32 + ot * 8 + 2 * (lane & 3);
            float bb0 = bias[oc], bb1 = bias[oc + 1];
            __nv_bfloat162 v0 = __floats2bfloat162_rn(acc[mt][ot][0] + bb0,
                                                      acc[mt][ot][1] + bb1);
            __nv_bfloat162 v1 = __floats2bfloat162_rn(acc[mt][ot][2] + bb0,
                                                      acc[mt][ot][3] + bb1);
            *(__nv_bfloat162*)&outp[(size_t)(b * N_ + n0 + r0)     * osize + oc] = v0;
            *(__nv_bfloat162*)&outp[(size_t)(b * N_ + n0 + r0 + 8) * osize + oc] = v1;
        }
    }
}

__global__ void __launch_bounds__(256) proj_qk_kernel(
    const float* __restrict__ f,
    const int* __restrict__ idx_out, const float* __restrict__ Wq, const float* __restrict__ bq,
    const int* __restrict__ idx_in,  const float* __restrict__ Wk, const float* __restrict__ bk)
{
    const int sel = blockIdx.y;
    proj_body<32>(f,
                  sel ? idx_in : idx_out,
                  sel ? Wk : Wq,
                  sel ? bk : bq,
                  sel ? g_K : g_Q,
                  FOUT_, 0, blockIdx.z, blockIdx.x * 128);
}

__global__ void __launch_bounds__(256) proj_v_kernel(
    const float* __restrict__ f, const int* __restrict__ idx_in,
    const float* __restrict__ Wv, const float* __restrict__ bv)
{
    proj_body<128>(f, idx_in, Wv, bv, g_V, DV_,
                   blockIdx.y * 128, blockIdx.z, blockIdx.x * 128);
}

// ============================================================
// HMMA flash attention, BQ=128, 256 threads, chunk-fused, 1 sync/tile.
// warp (r=wid&3, cw=wid>>2): rows 32r..32r+31 (2 m-tiles), d-cols 128cw..+127.
// Redundant S across cw pair (no P exchange). Per 16-kv chunk:
// S-MMA -> exp -> pack -> PV, so tensor/MUFU/LDS interleave in every window.
// 3-buffer K/V ring, prefetch distance 2; load(t+2) issued after the sync.
// SMEM: Q 128x80 | K 3x 64x80 | V 3x 64x528  = 126976 B
// ============================================================
#define QSTR  80
#define VSTR  528
#define SM_Q  0
#define SM_K  10240
#define KBUF  5120
#define SM_V  25600
#define VBUF  33792
#define SM_TOT 126976

__device__ __forceinline__ void load_kv(unsigned sb, int b, int t, int buf) {
    const int tid = threadIdx.x;
    {   // K tile: 64 rows x 4 chunks
        int row = tid >> 2, c = tid & 3;
        cpa16(sb + SM_K + buf * KBUF + row * QSTR + c * 16,
              g_K + ((size_t)b * N_ + t * 64 + row) * FOUT_ + c * 8);
    }
    const __nv_bfloat16* vg = g_V + ((size_t)b * N_ + t * 64) * DV_;
#pragma unroll
    for (int i = 0; i < 8; i++) {   // V tile: 64 rows x 32 chunks
        int e = tid + i * 256;
        int row = e >> 5, c = e & 31;
        cpa16(sb + SM_V + buf * VBUF + row * VSTR + c * 16, vg + row * DV_ + c * 8);
    }
}

__global__ void __launch_bounds__(256) flash_mma_kernel() {
    extern __shared__ __align__(128) char smem[];
    const unsigned sb = smem_u32(smem);
    const int tid  = threadIdx.x;
    const int wid  = tid >> 5, lane = tid & 31;
    const int r    = wid & 3;          // q-row group of 32
    const int cw   = wid >> 2;         // d half
    const int gid  = lane >> 2, tig = lane & 3;
    const int b    = blockIdx.y;
    const int q0   = blockIdx.x * 128;

    // prologue: [Q + K0 + V0] [K1 + V1]
#pragma unroll
    for (int i = 0; i < 2; i++) {
        int e = tid + i * 256;
        int row = e >> 2, c = e & 3;
        cpa16(sb + SM_Q + row * QSTR + c * 16,
              g_Q + ((size_t)b * N_ + q0 + row) * FOUT_ + c * 8);
    }
    load_kv(sb, b, 0, 0);  CP_COMMIT();
    load_kv(sb, b, 1, 1);  CP_COMMIT();

    float acc[2][16][4];
#pragma unroll
    for (int mt = 0; mt < 2; mt++)
#pragma unroll
        for (int i = 0; i < 16; i++)
#pragma unroll
            for (int j = 0; j < 4; j++) acc[mt][i][j] = 0.0f;
    float rs[2][2] = {{0.f, 0.f}, {0.f, 0.f}};
    unsigned qf[2][2][4];

    const unsigned vrow = (lane & 7) + ((lane >> 3) & 1) * 8;
    const unsigned vcolb = (cw * 128 + (lane >> 4) * 8) * 2;

    for (int t = 0; t < NT_; t++) {
        CP_WAIT1();                    // tile t resident (t+1 may fly)
        __syncthreads();               // + all warps done reading buf (t-1)%3

        // prefetch t+2 into buf (t-1)%3 (== (t+2)%3), freed by the sync above
        if (t + 2 < NT_) load_kv(sb, b, t + 2, (t + 2) % 3);
        CP_COMMIT();

        if (t == 0) {
#pragma unroll
            for (int mt = 0; mt < 2; mt++) {
                unsigned qbase = sb + SM_Q + (32 * r + 16 * mt + (lane & 15)) * QSTR;
                ldsm4(qf[mt][0], qbase + (lane >> 4) * 16);
                ldsm4(qf[mt][1], qbase + 32 + (lane >> 4) * 16);
            }
        }

        const unsigned kb = sb + SM_K + (t % 3) * KBUF;
        const unsigned vb = sb + SM_V + (t % 3) * VBUF;

        // ---- chunk-fused: per 16-kv chunk, S -> exp -> P -> PV ----
#pragma unroll
        for (int j = 0; j < 4; j++) {
            unsigned kfa[4], kfb[4];
            ldsm4(kfa, kb + (j * 16 +     (lane & 7)) * QSTR + ((lane >> 3) * 8) * 2);
            ldsm4(kfb, kb + (j * 16 + 8 + (lane & 7)) * QSTR + ((lane >> 3) * 8) * 2);
            unsigned P[2][4];
#pragma unroll
            for (int mt = 0; mt < 2; mt++) {
                float Sa[4] = {0.f, 0.f, 0.f, 0.f};
                float Sb[4] = {0.f, 0.f, 0.f, 0.f};
                mma16816(Sa, qf[mt][0], kfa);
                mma16816(Sa, qf[mt][1], kfa + 2);
                mma16816(Sb, qf[mt][0], kfb);
                mma16816(Sb, qf[mt][1], kfb + 2);
                float e0 = __expf(Sa[0]), e1 = __expf(Sa[1]);
                float e2 = __expf(Sa[2]), e3 = __expf(Sa[3]);
                float e4 = __expf(Sb[0]), e5 = __expf(Sb[1]);
                float e6 = __expf(Sb[2]), e7 = __expf(Sb[3]);
                rs[mt][0] += (e0 + e1) + (e4 + e5);
                rs[mt][1] += (e2 + e3) + (e6 + e7);
                P[mt][0] = pack_bf16x2(e0, e1);
                P[mt][1] = pack_bf16x2(e2, e3);
                P[mt][2] = pack_bf16x2(e4, e5);
                P[mt][3] = pack_bf16x2(e6, e7);
            }
#pragma unroll
            for (int p = 0; p < 8; p++) {
                unsigned vf[4];
                ldsm4t(vf, vb + (16 * j + vrow) * VSTR + vcolb + p * 32);
                mma16816(acc[0][2 * p],     P[0], vf);
                mma16816(acc[0][2 * p + 1], P[0], vf + 2);
                mma16816(acc[1][2 * p],     P[1], vf);
                mma16816(acc[1][2 * p + 1], P[1], vf + 2);
            }
        }
    }

    // rowsum reduce within quad (redundant S -> per-warp sums complete)
#pragma unroll
    for (int mt = 0; mt < 2; mt++)
#pragma unroll
        for (int h = 0; h < 2; h++) {
            rs[mt][h] += __shfl_xor_sync(0xFFFFFFFFu, rs[mt][h], 1);
            rs[mt][h] += __shfl_xor_sync(0xFFFFFFFFu, rs[mt][h], 2);
        }

#pragma unroll
    for (int mt = 0; mt < 2; mt++) {
        float inv0 = 1.0f / rs[mt][0], inv1 = 1.0f / rs[mt][1];
        float* og = g_O + ((size_t)b * N_ + q0 + 32 * r + 16 * mt + gid) * DV_ + cw * 128;
        float* og2 = og + 8 * DV_;
#pragma unroll
        for (int nt = 0; nt < 16; nt++) {
            int col = nt * 8 + 2 * tig;
            *(float2*)(og  + col) = make_float2(acc[mt][nt][0] * inv0, acc[mt][nt][1] * inv0);
            *(float2*)(og2 + col) = make_float2(acc[mt][nt][2] * inv1, acc[mt][nt][3] * inv1);
        }
    }
}

// ============================================================
// Epilogue: 4 elements per thread; map stores slot+1 (0 = keep f)
// ============================================================
__global__ void __launch_bounds__(256) epilogue_kernel(
    const float* __restrict__ f, const float* __restrict__ mask,
    const float* __restrict__ gamma, float* __restrict__ out)
{
    int q = blockIdx.x * 256 + threadIdx.x;      // quad index
    int gid = q * 4;
    int hw = gid % HW_;
    int bc = gid / HW_;
    int c  = bc % C_;
    int b  = bc / C_;

    float4 fv = *(const float4*)(f + gid);
    int4  mp = *(const int4*)(g_map + hw);
    float4 mk = *(const float4*)(mask + b * HW_ + hw);
    float g = gamma[0];

    const float* ob = g_O + (size_t)b * N_ * DV_ + c;
    float4 val;
    val.x = (mp.x > 0) ? ob[(size_t)(mp.x - 1) * DV_] : fv.x;
    val.y = (mp.y > 0) ? ob[(size_t)(mp.y - 1) * DV_] : fv.y;
    val.z = (mp.z > 0) ? ob[(size_t)(mp.z - 1) * DV_] : fv.z;
    val.w = (mp.w > 0) ? ob[(size_t)(mp.w - 1) * DV_] : fv.w;

    float4 o2;
    o2.x = val.x * (1.0f + (1.0f - mk.x) * g);
    o2.y = val.y * (1.0f + (1.0f - mk.y) * g);
    o2.z = val.z * (1.0f + (1.0f - mk.z) * g);
    o2.w = val.w * (1.0f + (1.0f - mk.w) * g);

    *(float4*)(out + gid)        = val;
    *(float4*)(out + gid + TOT_) = o2;
}

// ============================================================
// launch
// ============================================================
extern "C" void kernel_launch(void* const* d_in, const int* in_sizes, int n_in,
                              void* d_out, int out_size) {
    const float* f       = (const float*)d_in[0];
    const float* mask    = (const float*)d_in[1];
    const int*   idx_out = (const int*)d_in[2];
    const int*   idx_in  = (const int*)d_in[3];
    const float* Wq      = (const float*)d_in[4];
    const float* bq      = (const float*)d_in[5];
    const float* Wk      = (const float*)d_in[6];
    const float* bk      = (const float*)d_in[7];
    const float* Wv      = (const float*)d_in[8];
    const float* bv      = (const float*)d_in[9];
    const float* gamma   = (const float*)d_in[10];
    float* out = (float*)d_out;

    const int SM_P32  = 32 * 512 + 32768 + 512;    // 49664
    const int SM_P128 = 128 * 512 + 32768 + 512;   // 98816
    cudaFuncSetAttribute(proj_qk_kernel,
                         cudaFuncAttributeMaxDynamicSharedMemorySize, SM_P32);
    cudaFuncSetAttribute(proj_v_kernel,
                         cudaFuncAttributeMaxDynamicSharedMemorySize, SM_P128);
    cudaFuncSetAttribute(flash_mma_kernel,
                         cudaFuncAttributeMaxDynamicSharedMemorySize, SM_TOT);

    map_set_kernel<<<(N_ + 255) / 256, 256>>>(idx_out);

    proj_qk_kernel<<<dim3(N_ / 128, 2, B_), 256, SM_P32>>>(
        f, idx_out, Wq, bq, idx_in, Wk, bk);
    proj_v_kernel<<<dim3(N_ / 128, DV_ / 128, B_), 256, SM_P128>>>(f, idx_in, Wv, bv);

    flash_mma_kernel<<<dim3(N_ / 128, B_), 256, SM_TOT>>>();

    epilogue_kernel<<<TOT_ / 4 / 256, 256>>>(f, mask, gamma, out);
}

// round 17
// speedup vs baseline: 1.0325x; 1.0033x over previous
#include <cuda_runtime.h>
#include <cuda_bf16.h>

#define B_    4
#define C_    256
#define HW_   9216
#define N_    4608
#define FOUT_ 32
#define DV_   256
#define TOT_  (B_ * C_ * HW_)
#define NT_   72            // kv tiles of 64

// ---- scratch ----
__device__ __align__(16) __nv_bfloat16 g_Q[B_ * N_ * FOUT_];  // (b,n,32)
__device__ __align__(16) __nv_bfloat16 g_K[B_ * N_ * FOUT_];  // (b,n,32)
__device__ __align__(16) __nv_bfloat16 g_V[B_ * N_ * DV_];    // (b,n,256)
__device__ float g_O[B_ * N_ * DV_];
__device__ __align__(16) int g_map[HW_];   // zero-init; stores slot+1 (0 = none)

// ============================================================
// helpers (base-ISA only: ldmatrix + mma.sync, legal on compute_103)
// ============================================================
__device__ __forceinline__ unsigned smem_u32(const void* p) {
    unsigned a;
    asm("{ .reg .u64 t; cvta.to.shared.u64 t, %1; cvt.u32.u64 %0, t; }" : "=r"(a) : "l"(p));
    return a;
}
__device__ __forceinline__ void cpa16(unsigned dst, const void* src) {
    asm volatile("cp.async.cg.shared.global [%0], [%1], 16;" :: "r"(dst), "l"(src));
}
#define CP_COMMIT() asm volatile("cp.async.commit_group;" ::: "memory")
#define CP_WAIT1()  asm volatile("cp.async.wait_group 1;" ::: "memory")
#define CP_WAIT0()  asm volatile("cp.async.wait_group 0;" ::: "memory")

__device__ __forceinline__ void ldsm4(unsigned* r, unsigned a) {
    asm volatile("ldmatrix.sync.aligned.m8n8.x4.shared.b16 {%0,%1,%2,%3}, [%4];"
        : "=r"(r[0]), "=r"(r[1]), "=r"(r[2]), "=r"(r[3]) : "r"(a));
}
__device__ __forceinline__ void ldsm4t(unsigned* r, unsigned a) {
    asm volatile("ldmatrix.sync.aligned.m8n8.x4.trans.shared.b16 {%0,%1,%2,%3}, [%4];"
        : "=r"(r[0]), "=r"(r[1]), "=r"(r[2]), "=r"(r[3]) : "r"(a));
}
// D = A@B + D, m16n8k16, bf16 in, fp32 accum
__device__ __forceinline__ void mma16816(float* c, const unsigned* a, const unsigned* b) {
    asm volatile("mma.sync.aligned.m16n8k16.row.col.f32.bf16.bf16.f32 "
        "{%0,%1,%2,%3}, {%4,%5,%6,%7}, {%8,%9}, {%0,%1,%2,%3};"
        : "+f"(c[0]), "+f"(c[1]), "+f"(c[2]), "+f"(c[3])
        : "r"(a[0]), "r"(a[1]), "r"(a[2]), "r"(a[3]), "r"(b[0]), "r"(b[1]));
}
__device__ __forceinline__ unsigned pack_bf16x2(float lo, float hi) {
    unsigned r;
    asm("cvt.rn.bf16x2.f32 %0, %1, %2;" : "=r"(r) : "f"(hi), "f"(lo));  // hi<<16 | lo
    return r;
}

// ============================================================
// scatter map: one launch; g_map zero-init, store slot+1
// ============================================================
__global__ void map_set_kernel(const int* __restrict__ idx_out) {
    int n = blockIdx.x * blockDim.x + threadIdx.x;
    if (n < N_) g_map[idx_out[n]] = n + 1;
}

// ============================================================
// HMMA projection body (unchanged)
// ============================================================
template<int OTILE>
__device__ __forceinline__ void proj_body(
    const float* __restrict__ f, const int* __restrict__ idx,
    const float* __restrict__ W, const float* __restrict__ bias,
    __nv_bfloat16* outp, int osize, int o0, int b, int n0)
{
    extern __shared__ __align__(128) char ps[];
    const unsigned sb = smem_u32(ps);
    const unsigned ws = sb;                       // OTILE*512 bytes
    const unsigned xs = sb + OTILE * 512;         // 2 x 16384 bytes
    int* sidx = (int*)(ps + OTILE * 512 + 32768);

    const int tid = threadIdx.x, wid = tid >> 5, lane = tid & 31;

    constexpr int OW = (OTILE == 128) ? 4 : OTILE / 32;  // o-warps
    constexpr int MW = 8 / OW;                           // m-warps
    constexpr int MT = 128 / (MW * 16);                  // m-tiles per warp
    const int mw = wid % MW;
    const int ow = wid / MW;
    const int mbase = mw * 16 * MT;

    if (tid < 128) sidx[tid] = idx[n0 + tid];

    for (int o = wid; o < OTILE; o += 8) {
#pragma unroll
        for (int h = 0; h < 2; h++) {
            float4 wv = *(const float4*)&W[(size_t)(o0 + o) * C_ + (lane + 32 * h) * 4];
            unsigned p0 = pack_bf16x2(wv.x, wv.y);
            unsigned p1 = pack_bf16x2(wv.z, wv.w);
            int ch = (lane >> 1) + 16 * h;
            *(uint2*)(ps + o * 512 + ((ch ^ (o & 7)) * 16) + (lane & 1) * 8)
                = make_uint2(p0, p1);
        }
    }
    __syncthreads();

    const int gn  = tid & 127;
    const int gcb = tid >> 7;
    const float* fb = f + (size_t)b * C_ * HW_;
    const int gidx = sidx[gn];

    unsigned gr[4][4];
    auto do_gather = [&](int c0) {
#pragma unroll
        for (int i = 0; i < 4; i++) {
            int cbase = c0 + (gcb + 2 * i) * 8;
#pragma unroll
            for (int j = 0; j < 4; j++) {
                float a0 = fb[(size_t)(cbase + 2 * j)     * HW_ + gidx];
                float a1 = fb[(size_t)(cbase + 2 * j + 1) * HW_ + gidx];
                gr[i][j] = pack_bf16x2(a0, a1);
            }
        }
    };
    auto do_sts = [&](int buf) {
#pragma unroll
        for (int i = 0; i < 4; i++) {
            int ch = gcb + 2 * i;
            *(uint4*)(ps + OTILE * 512 + buf * 16384 + gn * 128 + ((ch ^ (gn & 7)) * 16))
                = make_uint4(gr[i][0], gr[i][1], gr[i][2], gr[i][3]);
        }
    };

    do_gather(0);
    do_sts(0);
    __syncthreads();

    float acc[MT][4][4];
#pragma unroll
    for (int mt = 0; mt < MT; mt++)
#pragma unroll
        for (int ot = 0; ot < 4; ot++)
#pragma unroll
            for (int j = 0; j < 4; j++) acc[mt][ot][j] = 0.0f;

    for (int c4 = 0; c4 < 4; c4++) {
        const int buf = c4 & 1;
        if (c4 < 3) do_gather((c4 + 1) * 64);

        const unsigned xb = xs + buf * 16384;
#pragma unroll
        for (int s = 0; s < 4; s++) {
            unsigned bf[2][4];
#pragma unroll
            for (int oh = 0; oh < 2; oh++) {
                int row = ow * 32 + oh * 16 + (lane & 15);
                int ch  = c4 * 8 + 2 * s + (lane >> 4);
                ldsm4(bf[oh], ws + row * 512 + ((ch ^ (row & 7)) * 16));
            }
#pragma unroll
            for (int mt = 0; mt < MT; mt++) {
                unsigned af[4];
                int row = mbase + 16 * mt + (lane & 15);
                int ch  = 2 * s + (lane >> 4);
                ldsm4(af, xb + row * 128 + ((ch ^ (row & 7)) * 16));
                unsigned b0[2] = { bf[0][0], bf[0][2] };
                unsigned b1[2] = { bf[0][1], bf[0][3] };
                unsigned b2[2] = { bf[1][0], bf[1][2] };
                unsigned b3[2] = { bf[1][1], bf[1][3] };
                mma16816(acc[mt][0], af, b0);
                mma16816(acc[mt][1], af, b1);
                mma16816(acc[mt][2], af, b2);
                mma16816(acc[mt][3], af, b3);
            }
        }
        if (c4 < 3) do_sts(buf ^ 1);
        __syncthreads();
    }

#pragma unroll
    for (int mt = 0; mt < MT; mt++) {
        int r0 = mbase + 16 * mt + (lane >> 2);
#pragma unroll
        for (int ot = 0; ot < 4; ot++) {
            int oc = o0 + ow * 32 + ot * 8 + 2 * (lane & 3);
            float bb0 = bias[oc], bb1 = bias[oc + 1];
            __nv_bfloat162 v0 = __floats2bfloat162_rn(acc[mt][ot][0] + bb0,
                                                      acc[mt][ot][1] + bb1);
            __nv_bfloat162 v1 = __floats2bfloat162_rn(acc[mt][ot][2] + bb0,
                                                      acc[mt][ot][3] + bb1);
            *(__nv_bfloat162*)&outp[(size_t)(b * N_ + n0 + r0)     * osize + oc] = v0;
            *(__nv_bfloat162*)&outp[(size_t)(b * N_ + n0 + r0 + 8) * osize + oc] = v1;
        }
    }
}

__global__ void __launch_bounds__(256) proj_qk_kernel(
    const float* __restrict__ f,
    const int* __restrict__ idx_out, const float* __restrict__ Wq, const float* __restrict__ bq,
    const int* __restrict__ idx_in,  const float* __restrict__ Wk, const float* __restrict__ bk)
{
    const int sel = blockIdx.y;
    proj_body<32>(f,
                  sel ? idx_in : idx_out,
                  sel ? Wk : Wq,
                  sel ? bk : bq,
                  sel ? g_K : g_Q,
                  FOUT_, 0, blockIdx.z, blockIdx.x * 128);
}

__global__ void __launch_bounds__(256) proj_v_kernel(
    const float* __restrict__ f, const int* __restrict__ idx_in,
    const float* __restrict__ Wv, const float* __restrict__ bv)
{
    proj_body<128>(f, idx_in, Wv, bv, g_V, DV_,
                   blockIdx.y * 128, blockIdx.z, blockIdx.x * 128);
}

// ============================================================
// HMMA flash attention, BQ=128, 256 threads, chunk-fused.
// NEW (R14): 4-buffer K/V ring, __syncthreads only at EVEN tiles,
// preceded by cp.async.wait_group 0 (cross-thread visibility for the
// next TWO tiles). Warps may drift one tile apart between barriers,
// desynchronizing exp/PV phases across the 2 warps per SMSP so the
// tensor pipe stays fed during MUFU stretches.
// Safety: drift bounded by the barrier; load(t+2)->buf (t+2)%4 whose
// last reader finished at t-2 (before previous barrier); (t-1)%4 is
// distinct from t%4 and (t+1)%4 so prefetch never collides with a
// trailing reader.
// SMEM: Q 128x80 | K 4x 64x80 | V 4x 64x528  = 165888 B
// ============================================================
#define QSTR  80
#define VSTR  528
#define SM_Q  0
#define SM_K  10240
#define KBUF  5120
#define SM_V  30720
#define VBUF  33792
#define SM_TOT 165888

__device__ __forceinline__ void load_kv(unsigned sb, int b, int t, int buf) {
    const int tid = threadIdx.x;
    {   // K tile: 64 rows x 4 chunks
        int row = tid >> 2, c = tid & 3;
        cpa16(sb + SM_K + buf * KBUF + row * QSTR + c * 16,
              g_K + ((size_t)b * N_ + t * 64 + row) * FOUT_ + c * 8);
    }
    const __nv_bfloat16* vg = g_V + ((size_t)b * N_ + t * 64) * DV_;
#pragma unroll
    for (int i = 0; i < 8; i++) {   // V tile: 64 rows x 32 chunks
        int e = tid + i * 256;
        int row = e >> 5, c = e & 31;
        cpa16(sb + SM_V + buf * VBUF + row * VSTR + c * 16, vg + row * DV_ + c * 8);
    }
}

__global__ void __launch_bounds__(256) flash_mma_kernel() {
    extern __shared__ __align__(128) char smem[];
    const unsigned sb = smem_u32(smem);
    const int tid  = threadIdx.x;
    const int wid  = tid >> 5, lane = tid & 31;
    const int r    = wid & 3;          // q-row group of 32
    const int cw   = wid >> 2;         // d half
    const int gid  = lane >> 2, tig = lane & 3;
    const int b    = blockIdx.y;
    const int q0   = blockIdx.x * 128;

    // prologue: [Q + K0 + V0] [K1 + V1]
#pragma unroll
    for (int i = 0; i < 2; i++) {
        int e = tid + i * 256;
        int row = e >> 2, c = e & 3;
        cpa16(sb + SM_Q + row * QSTR + c * 16,
              g_Q + ((size_t)b * N_ + q0 + row) * FOUT_ + c * 8);
    }
    load_kv(sb, b, 0, 0);  CP_COMMIT();
    load_kv(sb, b, 1, 1);  CP_COMMIT();

    float acc[2][16][4];
#pragma unroll
    for (int mt = 0; mt < 2; mt++)
#pragma unroll
        for (int i = 0; i < 16; i++)
#pragma unroll
            for (int j = 0; j < 4; j++) acc[mt][i][j] = 0.0f;
    float rs[2][2] = {{0.f, 0.f}, {0.f, 0.f}};
    unsigned qf[2][2][4];

    const unsigned vrow = (lane & 7) + ((lane >> 3) & 1) * 8;
    const unsigned vcolb = (cw * 128 + (lane >> 4) * 8) * 2;

    for (int t = 0; t < NT_; t++) {
        if ((t & 1) == 0) {
            CP_WAIT0();                // ALL loads for tiles t, t+1 complete
            __syncthreads();           // visible to every warp; drift reset
        }

        // prefetch t+2 into buf (t+2)&3 (last read at t-2, pre-barrier)
        if (t + 2 < NT_) { load_kv(sb, b, t + 2, (t + 2) & 3); CP_COMMIT(); }

        if (t == 0) {
#pragma unroll
            for (int mt = 0; mt < 2; mt++) {
                unsigned qbase = sb + SM_Q + (32 * r + 16 * mt + (lane & 15)) * QSTR;
                ldsm4(qf[mt][0], qbase + (lane >> 4) * 16);
                ldsm4(qf[mt][1], qbase + 32 + (lane >> 4) * 16);
            }
        }

        const unsigned kb = sb + SM_K + (t & 3) * KBUF;
        const unsigned vb = sb + SM_V + (t & 3) * VBUF;

        // ---- chunk-fused: per 16-kv chunk, S -> exp -> P -> PV ----
#pragma unroll
        for (int j = 0; j < 4; j++) {
            unsigned kfa[4], kfb[4];
            ldsm4(kfa, kb + (j * 16 +     (lane & 7)) * QSTR + ((lane >> 3) * 8) * 2);
            ldsm4(kfb, kb + (j * 16 + 8 + (lane & 7)) * QSTR + ((lane >> 3) * 8) * 2);
            unsigned P[2][4];
#pragma unroll
            for (int mt = 0; mt < 2; mt++) {
                float Sa[4] = {0.f, 0.f, 0.f, 0.f};
                float Sb[4] = {0.f, 0.f, 0.f, 0.f};
                mma16816(Sa, qf[mt][0], kfa);
                mma16816(Sa, qf[mt][1], kfa + 2);
                mma16816(Sb, qf[mt][0], kfb);
                mma16816(Sb, qf[mt][1], kfb + 2);
                float e0 = __expf(Sa[0]), e1 = __expf(Sa[1]);
                float e2 = __expf(Sa[2]), e3 = __expf(Sa[3]);
                float e4 = __expf(Sb[0]), e5 = __expf(Sb[1]);
                float e6 = __expf(Sb[2]), e7 = __expf(Sb[3]);
                rs[mt][0] += (e0 + e1) + (e4 + e5);
                rs[mt][1] += (e2 + e3) + (e6 + e7);
                P[mt][0] = pack_bf16x2(e0, e1);
                P[mt][1] = pack_bf16x2(e2, e3);
                P[mt][2] = pack_bf16x2(e4, e5);
                P[mt][3] = pack_bf16x2(e6, e7);
            }
#pragma unroll
            for (int p = 0; p < 8; p++) {
                unsigned vf[4];
                ldsm4t(vf, vb + (16 * j + vrow) * VSTR + vcolb + p * 32);
                mma16816(acc[0][2 * p],     P[0], vf);
                mma16816(acc[0][2 * p + 1], P[0], vf + 2);
                mma16816(acc[1][2 * p],     P[1], vf);
                mma16816(acc[1][2 * p + 1], P[1], vf + 2);
            }
        }
    }

    // rowsum reduce within quad (redundant S -> per-warp sums complete)
#pragma unroll
    for (int mt = 0; mt < 2; mt++)
#pragma unroll
        for (int h = 0; h < 2; h++) {
            rs[mt][h] += __shfl_xor_sync(0xFFFFFFFFu, rs[mt][h], 1);
            rs[mt][h] += __shfl_xor_sync(0xFFFFFFFFu, rs[mt][h], 2);
        }

#pragma unroll
    for (int mt = 0; mt < 2; mt++) {
        float inv0 = 1.0f / rs[mt][0], inv1 = 1.0f / rs[mt][1];
        float* og = g_O + ((size_t)b * N_ + q0 + 32 * r + 16 * mt + gid) * DV_ + cw * 128;
        float* og2 = og + 8 * DV_;
#pragma unroll
        for (int nt = 0; nt < 16; nt++) {
            int col = nt * 8 + 2 * tig;
            *(float2*)(og  + col) = make_float2(acc[mt][nt][0] * inv0, acc[mt][nt][1] * inv0);
            *(float2*)(og2 + col) = make_float2(acc[mt][nt][2] * inv1, acc[mt][nt][3] * inv1);
        }
    }
}

// ============================================================
// Epilogue: 4 elements per thread; map stores slot+1 (0 = keep f)
// ============================================================
__global__ void __launch_bounds__(256) epilogue_kernel(
    const float* __restrict__ f, const float* __restrict__ mask,
    const float* __restrict__ gamma, float* __restrict__ out)
{
    int q = blockIdx.x * 256 + threadIdx.x;      // quad index
    int gid = q * 4;
    int hw = gid % HW_;
    int bc = gid / HW_;
    int c  = bc % C_;
    int b  = bc / C_;

    float4 fv = *(const float4*)(f + gid);
    int4  mp = *(const int4*)(g_map + hw);
    float4 mk = *(const float4*)(mask + b * HW_ + hw);
    float g = gamma[0];

    const float* ob = g_O + (size_t)b * N_ * DV_ + c;
    float4 val;
    val.x = (mp.x > 0) ? ob[(size_t)(mp.x - 1) * DV_] : fv.x;
    val.y = (mp.y > 0) ? ob[(size_t)(mp.y - 1) * DV_] : fv.y;
    val.z = (mp.z > 0) ? ob[(size_t)(mp.z - 1) * DV_] : fv.z;
    val.w = (mp.w > 0) ? ob[(size_t)(mp.w - 1) * DV_] : fv.w;

    float4 o2;
    o2.x = val.x * (1.0f + (1.0f - mk.x) * g);
    o2.y = val.y * (1.0f + (1.0f - mk.y) * g);
    o2.z = val.z * (1.0f + (1.0f - mk.z) * g);
    o2.w = val.w * (1.0f + (1.0f - mk.w) * g);

    *(float4*)(out + gid)        = val;
    *(float4*)(out + gid + TOT_) = o2;
}

// ============================================================
// launch
// ============================================================
extern "C" void kernel_launch(void* const* d_in, const int* in_sizes, int n_in,
                              void* d_out, int out_size) {
    const float* f       = (const float*)d_in[0];
    const float* mask    = (const float*)d_in[1];
    const int*   idx_out = (const int*)d_in[2];
    const int*   idx_in  = (const int*)d_in[3];
    const float* Wq      = (const float*)d_in[4];
    const float* bq      = (const float*)d_in[5];
    const float* Wk      = (const float*)d_in[6];
    const float* bk      = (const float*)d_in[7];
    const float* Wv      = (const float*)d_in[8];
    const float* bv      = (const float*)d_in[9];
    const float* gamma   = (const float*)d_in[10];
    float* out = (float*)d_out;

    const int SM_P32  = 32 * 512 + 32768 + 512;    // 49664
    const int SM_P128 = 128 * 512 + 32768 + 512;   // 98816
    cudaFuncSetAttribute(proj_qk_kernel,
                         cudaFuncAttributeMaxDynamicSharedMemorySize, SM_P32);
    cudaFuncSetAttribute(proj_v_kernel,
                         cudaFuncAttributeMaxDynamicSharedMemorySize, SM_P128);
    cudaFuncSetAttribute(flash_mma_kernel,
                         cudaFuncAttributeMaxDynamicSharedMemorySize, SM_TOT);

    map_set_kernel<<<(N_ + 255) / 256, 256>>>(idx_out);

    proj_qk_kernel<<<dim3(N_ / 128, 2, B_), 256, SM_P32>>>(
        f, idx_out, Wq, bq, idx_in, Wk, bk);
    proj_v_kernel<<<dim3(N_ / 128, DV_ / 128, B_), 256, SM_P128>>>(f, idx_in, Wv, bv);

    flash_mma_kernel<<<dim3(N_ / 128, B_), 256, SM_TOT>>>();

    epilogue_kernel<<<TOT_ / 4 / 256, 256>>>(f, mask, gamma, out);
}